// round 14
// baseline (speedup 1.0000x reference)
#include <cuda_runtime.h>
#include <cuda_bf16.h>
#include <math_constants.h>

// Rejection sampler for speculative decoding (vLLM-style).
// grid = (SPLIT, B). Recovery-row argmax is split across SPLIT blocks and
// combined via u64 atomicMax; the last-arriving block finishes the row.
// The streaming loop uses cp.async (LDGSTS) 6-stage pipelining so that
// in-flight bytes live in the async queue + SMEM instead of registers
// (ptxas refuses to hold >1-2 LDG results live in this loop; measured
// effective MLP~1 capped DRAM at ~1.5 TB/s in R8-R12).
// Output: [B, L+1] written as FLOAT32 (harness __output__ dtype).

#define SPLIT   8
#define THREADS 256
#define STAGES  6
#define MAXL    64
#define MAXB    8192

typedef unsigned long long u64;
typedef unsigned int       u32;

// zero-initialized at load; reset by the finisher each run => graph-replay safe
__device__ u64 g_key[MAXB];
__device__ u32 g_cnt[MAXB];

__device__ __forceinline__ u32 smem_u32(const void* p) {
    return (u32)__cvta_generic_to_shared(p);
}

__global__ __launch_bounds__(THREADS)
void rejection_sample_kernel(const float* __restrict__ draft_probs,
                             const float* __restrict__ target_probs,
                             const void*  __restrict__ ntA,   // draft_ids OR uniform
                             const void*  __restrict__ ntB,   // the other one
                             const int*   __restrict__ bA,    // cu OR bonus
                             const int*   __restrict__ bB,    // the other one
                             float*       __restrict__ out,   // FLOAT output
                             int NT, int V, int L, int B)
{
    const int slice = blockIdx.x;            // 0..SPLIT-1
    const int b     = blockIdx.y;            // request
    const int tid   = threadIdx.x;
    if (b >= B) return;

    __shared__ uint4 sbuf[STAGES][THREADS];  // cp.async staging (24 KB)
    __shared__ float s_tp[MAXL], s_dp[MAXL], s_u[MAXL];
    __shared__ int   s_tok[MAXL];
    __shared__ int   s_last, s_rej, s_rec;
    __shared__ u64   s_key[THREADS / 32];

    // ---- device-side content disambiguation (L2-cached, deterministic) ----
    const unsigned* pa = (const unsigned*)ntA;
    bool a_is_ids = true;
    #pragma unroll
    for (int i = 0; i < 4; ++i) {
        const int pi = (NT > 1) ? (int)(((long long)i * (NT - 1)) / 3) : 0;
        if (pa[pi] >= 0x00400000u) a_is_ids = false;
    }
    const int*   draft_ids     = a_is_ids ? (const int*)ntA   : (const int*)ntB;
    const float* uniform_probs = a_is_ids ? (const float*)ntB : (const float*)ntA;

    const int lastA = bA[B - 1], lastB = bB[B - 1];
    const int *cu, *bonus;
    if (lastA == NT && lastB != NT)      { cu = bA; bonus = bB; }
    else if (lastB == NT && lastA != NT) { cu = bB; bonus = bA; }
    else {
        cu = (bA[0] >= 0 && bA[0] <= lastA && lastA <= NT) ? bA : bB;
        bonus = (cu == bA) ? bB : bA;
    }

    int start = (b == 0) ? 0 : cu[b - 1];
    start = max(0, min(start, NT));
    int nd = cu[b] - start;
    nd = max(0, min(nd, NT - start));
    const int ndc = min(min(nd, L), MAXL);

    // --- Phase 1: parallel gather ---
    if (tid < ndc) {
        const int idx = min(start + tid, NT - 1);
        int tok = draft_ids[idx];
        tok = max(0, min(tok, V - 1));
        s_tok[tid] = tok;
        s_tp[tid]  = target_probs[(size_t)idx * V + tok];
        s_dp[tid]  = draft_probs [(size_t)idx * V + tok];
        s_u[tid]   = uniform_probs[idx];
    }
    __syncthreads();

    // --- Phase 2: exact replay of the reference scan (thread 0) ---
    if (tid == 0) {
        float pi = 1.0f, U = 1.0f;
        int last = -1;
        for (int l = 0; l < ndc; ++l) {
            const float dp = s_dp[l];
            const bool  ok = (dp > 0.0f);
            const float r  = ok ? __fdiv_rn(s_tp[l], dp) : 1.0f;  // IEEE RN
            pi = fminf(__fmul_rn(pi, r), 1.0f);
            U  = __fmul_rn(U, s_u[l]);
            if (ok && pi >= U) last = l;   // scan does NOT stop at first reject
        }
        const int rej = (nd > 0) && (last != nd - 1);
        int rec = start + last + 1;
        rec = max(0, min(rec, NT - 1));
        s_last = last;
        s_rej  = rej;
        s_rec  = rec;

        if (slice == 0) {
            float* o = out + (size_t)b * (L + 1);
            for (int c = 0; c <= L; ++c) {
                if (rej && c == last + 1) continue;   // finisher writes that cell
                o[c] = (c < L && c <= last && c < MAXL) ? (float)s_tok[c] : -1.0f;
            }
            if (!rej)
                o[min(nd, L)] = (float)bonus[b];
        }
    }
    __syncthreads();

    const bool split_ok = (b < MAXB);

    // --- Phase 3: sliced argmax via cp.async staged streaming ---
    // probs >= 0 -> f32 bits monotone under unsigned compare.
    // key = (bits<<32) | ~idx : u64-max == argmax w/ first-occurrence ties.
    if (s_rej) {
        const uint4* row4 = (const uint4*)(target_probs + (size_t)s_rec * V);
        const int n4 = V >> 2;
        int lo, hi;
        if (split_ok) {
            lo = (int)(((long long)slice       * n4) / SPLIT);
            hi = (int)(((long long)(slice + 1) * n4) / SPLIT);
        } else {
            lo = 0; hi = (slice == 0) ? n4 : 0;
        }
        const int ntiles = (hi - lo + THREADS - 1) / THREADS;

        // Prologue: exactly STAGES commit groups (empty groups complete at once)
        #pragma unroll
        for (int s = 0; s < STAGES; ++s) {
            const int idx = lo + s * THREADS + tid;
            if (s < ntiles && idx < hi) {
                const u32 dst = smem_u32(&sbuf[s][tid]);
                asm volatile("cp.async.cg.shared.global [%0], [%1], 16;"
                             :: "r"(dst), "l"(row4 + idx));
            }
            asm volatile("cp.async.commit_group;");
        }

        u64 k0 = 0, k1 = 0, k2 = 0, k3 = 0;
        for (int t = 0; t < ntiles; ++t) {
            // before consuming tile t: commits = STAGES + t, allow STAGES-1
            // pending => groups 0..t retired => tile t's data is in SMEM.
            asm volatile("cp.async.wait_group %0;" :: "n"(STAGES - 1));
            const int idx = lo + t * THREADS + tid;
            if (idx < hi) {
                const uint4 v = sbuf[t % STAGES][tid];   // own slot; no barrier needed
                const u32 nb = ~(u32)(idx << 2);
                const u64 c0 = ((u64)v.x << 32) | nb;
                const u64 c1 = ((u64)v.y << 32) | (nb - 1u);
                const u64 c2 = ((u64)v.z << 32) | (nb - 2u);
                const u64 c3 = ((u64)v.w << 32) | (nb - 3u);
                if (c0 > k0) k0 = c0;
                if (c1 > k1) k1 = c1;
                if (c2 > k2) k2 = c2;
                if (c3 > k3) k3 = c3;
            }
            const int nt2  = t + STAGES;
            const int idx2 = lo + nt2 * THREADS + tid;
            if (nt2 < ntiles && idx2 < hi) {
                const u32 dst = smem_u32(&sbuf[nt2 % STAGES][tid]);
                asm volatile("cp.async.cg.shared.global [%0], [%1], 16;"
                             :: "r"(dst), "l"(row4 + idx2));
            }
            asm volatile("cp.async.commit_group;");
        }

        // scalar tail (V % 4) handled by the last slice
        if ((split_ok ? (slice == SPLIT - 1) : (slice == 0))) {
            const float* rowf = (const float*)row4;
            for (int i = (n4 << 2) + tid; i < V; i += THREADS) {
                const u64 c = ((u64)__float_as_uint(rowf[i]) << 32) | ~(u32)i;
                if (c > k0) k0 = c;
            }
        }

        u64 best = k0;
        if (k1 > best) best = k1;
        if (k2 > best) best = k2;
        if (k3 > best) best = k3;

        #pragma unroll
        for (int off = 16; off; off >>= 1) {
            const u64 o64 = __shfl_xor_sync(0xffffffff, best, off);
            if (o64 > best) best = o64;
        }
        const int wid  = tid >> 5;
        const int lane = tid & 31;
        if (lane == 0) s_key[wid] = best;
        __syncthreads();
        if (wid == 0) {
            constexpr int NW = THREADS / 32;
            best = (lane < NW) ? s_key[lane] : 0ull;
            #pragma unroll
            for (int off = 16; off; off >>= 1) {
                const u64 o64 = __shfl_xor_sync(0xffffffff, best, off);
                if (o64 > best) best = o64;
            }
            if (lane == 0) {
                if (split_ok)        atomicMax(&g_key[b], best);
                else if (slice == 0)
                    out[(size_t)b * (L + 1) + (s_last + 1)] = (float)(int)(~(u32)best);
            }
        }
    }

    // --- Completion: last-arriving block finishes + resets scratch ---
    if (split_ok && tid == 0) {
        __threadfence();
        const u32 old = atomicAdd(&g_cnt[b], 1u);
        if (old == SPLIT - 1) {
            if (s_rej) {
                const u64 key = atomicMax(&g_key[b], 0ull);   // read combined max
                out[(size_t)b * (L + 1) + (s_last + 1)] = (float)(int)(~(u32)key);
            }
            g_key[b] = 0ull;     // restore for next run (graph replay safe)
            g_cnt[b] = 0u;
        }
    }
}

extern "C" void kernel_launch(void* const* d_in, const int* in_sizes, int n_in,
                              void* d_out, int out_size)
{
    // ---- order-agnostic slot resolution from sizes ----
    long long sz[6];
    for (int i = 0; i < 6; ++i) sz[i] = (i < n_in) ? (long long)in_sizes[i] : 0;

    long long mx = 0;
    for (int i = 0; i < 6; ++i) mx = (sz[i] > mx) ? sz[i] : mx;
    int ip[2], npb = 0;
    for (int i = 0; i < 6 && npb < 2; ++i) if (sz[i] == mx) ip[npb++] = i;
    if (npb < 2) ip[1] = ip[0];

    int rest[4], nr = 0;
    for (int i = 0; i < 6; ++i) if (i != ip[0] && i != ip[1] && nr < 4) rest[nr++] = i;

    long long vA = sz[rest[0]], vB = -1;
    for (int j = 1; j < 4; ++j) if (sz[rest[j]] != vA) { vB = sz[rest[j]]; break; }
    long long Bv, NTv;
    if (vB < 0) { Bv = vA; NTv = vA; }
    else {
        const bool aOK = (vA > 0) && (out_size % vA == 0) && (out_size / vA >= 2);
        const bool bOK = (vB > 0) && (out_size % vB == 0) && (out_size / vB >= 2);
        if (aOK && !bOK)      Bv = vA;
        else if (bOK && !aOK) Bv = vB;
        else                  Bv = (vA < vB) ? vA : vB;   // B <= NT
        NTv = (Bv == vA) ? vB : vA;
    }

    int iNT[2], iB[2]; int nnt = 0, nb = 0;
    for (int j = 0; j < 4; ++j) {
        if (sz[rest[j]] == NTv && nnt < 2)      iNT[nnt++] = rest[j];
        else if (nb < 2)                        iB[nb++]  = rest[j];
    }
    if (nnt < 2) iNT[1] = iNT[0];
    if (nb  < 1) { iB[0] = iNT[0]; iB[1] = iNT[1]; }
    else if (nb < 2) iB[1] = iB[0];

    const int NT = (int)NTv;
    const int B  = (int)Bv;
    const int V  = (int)(mx / (NTv > 0 ? NTv : 1));
    int L = (B > 0) ? (out_size / B - 1) : 4;
    if (L < 1) L = 1;

    dim3 grid(SPLIT, (B > 0 ? B : 1), 1);
    rejection_sample_kernel<<<grid, THREADS>>>(
        (const float*)d_in[ip[0]], (const float*)d_in[ip[1]],
        d_in[iNT[0]], d_in[iNT[1]],
        (const int*)d_in[iB[0]], (const int*)d_in[iB[1]],
        (float*)d_out, NT, V, L, B);
}

// round 15
// speedup vs baseline: 1.3208x; 1.3208x over previous
#include <cuda_runtime.h>
#include <cuda_bf16.h>
#include <math_constants.h>

// Rejection sampler for speculative decoding (vLLM-style).
// grid = (SPLIT, B). Recovery-row argmax split across SPLIT blocks, combined
// via u64 atomicMax on device scratch; last-arriving block finishes the row.
// Hot loop is an f32 max-tree (3 FMNMX + 1 compare per quad) with a rare
// index-resolve path -- the previous u64 packed-key compare cost ~28 ALU
// lane-ops per quad and was the real bottleneck (ALU-bound on active SMs;
// data is L2-resident across graph replays, so bandwidth never mattered).
// Output: [B, L+1] written as FLOAT32 (harness __output__ dtype).

#define SPLIT   8
#define THREADS 256
#define MAXL    64
#define MAXB    8192

typedef unsigned long long u64;
typedef unsigned int       u32;

// zero-initialized at load; reset by the finisher each run => graph-replay safe
__device__ u64 g_key[MAXB];
__device__ u32 g_cnt[MAXB];

__global__ __launch_bounds__(THREADS)
void rejection_sample_kernel(const float* __restrict__ draft_probs,
                             const float* __restrict__ target_probs,
                             const void*  __restrict__ ntA,   // draft_ids OR uniform
                             const void*  __restrict__ ntB,   // the other one
                             const int*   __restrict__ bA,    // cu OR bonus
                             const int*   __restrict__ bB,    // the other one
                             float*       __restrict__ out,   // FLOAT output
                             int NT, int V, int L, int B)
{
    const int slice = blockIdx.x;            // 0..SPLIT-1
    const int b     = blockIdx.y;            // request
    const int tid   = threadIdx.x;
    if (b >= B) return;

    // ---- device-side content disambiguation (L2-cached, deterministic) ----
    const unsigned* pa = (const unsigned*)ntA;
    bool a_is_ids = true;
    #pragma unroll
    for (int i = 0; i < 4; ++i) {
        const int pi = (NT > 1) ? (int)(((long long)i * (NT - 1)) / 3) : 0;
        if (pa[pi] >= 0x00400000u) a_is_ids = false;
    }
    const int*   draft_ids     = a_is_ids ? (const int*)ntA   : (const int*)ntB;
    const float* uniform_probs = a_is_ids ? (const float*)ntB : (const float*)ntA;

    const int lastA = bA[B - 1], lastB = bB[B - 1];
    const int *cu, *bonus;
    if (lastA == NT && lastB != NT)      { cu = bA; bonus = bB; }
    else if (lastB == NT && lastA != NT) { cu = bB; bonus = bA; }
    else {
        cu = (bA[0] >= 0 && bA[0] <= lastA && lastA <= NT) ? bA : bB;
        bonus = (cu == bA) ? bB : bA;
    }

    __shared__ float s_tp[MAXL], s_dp[MAXL], s_u[MAXL];
    __shared__ int   s_tok[MAXL];
    __shared__ int   s_last, s_rej, s_rec;
    __shared__ u64   s_key[THREADS / 32];

    int start = (b == 0) ? 0 : cu[b - 1];
    start = max(0, min(start, NT));
    int nd = cu[b] - start;
    nd = max(0, min(nd, NT - start));
    const int ndc = min(min(nd, L), MAXL);

    // --- Phase 1: parallel gather ---
    if (tid < ndc) {
        const int idx = min(start + tid, NT - 1);
        int tok = draft_ids[idx];
        tok = max(0, min(tok, V - 1));
        s_tok[tid] = tok;
        s_tp[tid]  = target_probs[(size_t)idx * V + tok];
        s_dp[tid]  = draft_probs [(size_t)idx * V + tok];
        s_u[tid]   = uniform_probs[idx];
    }
    __syncthreads();

    // --- Phase 2: exact replay of the reference scan (thread 0) ---
    if (tid == 0) {
        float pi = 1.0f, U = 1.0f;
        int last = -1;
        for (int l = 0; l < ndc; ++l) {
            const float dp = s_dp[l];
            const bool  ok = (dp > 0.0f);
            const float r  = ok ? __fdiv_rn(s_tp[l], dp) : 1.0f;  // IEEE RN
            pi = fminf(__fmul_rn(pi, r), 1.0f);
            U  = __fmul_rn(U, s_u[l]);
            if (ok && pi >= U) last = l;   // scan does NOT stop at first reject
        }
        const int rej = (nd > 0) && (last != nd - 1);
        int rec = start + last + 1;
        rec = max(0, min(rec, NT - 1));
        s_last = last;
        s_rej  = rej;
        s_rec  = rec;

        if (slice == 0) {
            float* o = out + (size_t)b * (L + 1);
            for (int c = 0; c <= L; ++c) {
                if (rej && c == last + 1) continue;   // finisher writes that cell
                o[c] = (c < L && c <= last && c < MAXL) ? (float)s_tok[c] : -1.0f;
            }
            if (!rej)
                o[min(nd, L)] = (float)bonus[b];
        }
    }
    __syncthreads();

    const bool split_ok = (b < MAXB);

    // --- Phase 3: sliced argmax, f32 max-tree hot loop ---
    if (s_rej) {
        const float4* row4 = (const float4*)(target_probs + (size_t)s_rec * V);
        const int n4 = V >> 2;
        int lo, hi;
        if (split_ok) {
            lo = (int)(((long long)slice       * n4) / SPLIT);
            hi = (int)(((long long)(slice + 1) * n4) / SPLIT);
        } else {
            lo = 0; hi = (slice == 0) ? n4 : 0;
        }

        // Two independent chains (MLP=2). Strict '>' keeps the first
        // occurrence within each ascending chain.
        float best0 = -1.0f, best1 = -1.0f;
        int   bidx0 = 0x7fffffff, bidx1 = 0x7fffffff;
        const float4 pad = make_float4(-1.0f, -1.0f, -1.0f, -1.0f);

        for (int i = lo + tid; i < hi; i += THREADS * 2) {
            const int i2 = i + THREADS;
            const float4 va = __ldg(&row4[i]);
            const float4 vb = (i2 < hi) ? __ldg(&row4[i2]) : pad;

            const float ma = fmaxf(fmaxf(va.x, va.y), fmaxf(va.z, va.w));
            if (ma > best0) {            // rare (~ln(n) per thread)
                best0 = ma;
                const int base = i << 2;
                bidx0 = (va.x == ma) ? base
                      : (va.y == ma) ? base + 1
                      : (va.z == ma) ? base + 2 : base + 3;
            }
            const float mb = fmaxf(fmaxf(vb.x, vb.y), fmaxf(vb.z, vb.w));
            if (mb > best1) {
                best1 = mb;
                const int base = i2 << 2;
                bidx1 = (vb.x == mb) ? base
                      : (vb.y == mb) ? base + 1
                      : (vb.z == mb) ? base + 2 : base + 3;
            }
        }
        // merge chains (smaller index wins ties)
        if (best1 > best0 || (best1 == best0 && bidx1 < bidx0)) {
            best0 = best1; bidx0 = bidx1;
        }
        // scalar tail (V % 4) handled by the last slice
        if ((split_ok ? (slice == SPLIT - 1) : (slice == 0))) {
            const float* rowf = (const float*)row4;
            for (int i = (n4 << 2) + tid; i < V; i += THREADS) {
                const float v = rowf[i];
                if (v > best0) { best0 = v; bidx0 = i; }
            }
        }

        // pack once per thread: probs >= 0 -> f32 bits monotone unsigned;
        // key = (bits<<32) | ~idx; threads with no data get key 0.
        u64 best = (bidx0 == 0x7fffffff)
                 ? 0ull
                 : (((u64)__float_as_uint(best0) << 32) | (u32)~(u32)bidx0);

        #pragma unroll
        for (int off = 16; off; off >>= 1) {
            const u64 o64 = __shfl_xor_sync(0xffffffff, best, off);
            if (o64 > best) best = o64;
        }
        const int wid  = tid >> 5;
        const int lane = tid & 31;
        if (lane == 0) s_key[wid] = best;
        __syncthreads();
        if (wid == 0) {
            constexpr int NW = THREADS / 32;
            best = (lane < NW) ? s_key[lane] : 0ull;
            #pragma unroll
            for (int off = 16; off; off >>= 1) {
                const u64 o64 = __shfl_xor_sync(0xffffffff, best, off);
                if (o64 > best) best = o64;
            }
            if (lane == 0) {
                if (split_ok)        atomicMax(&g_key[b], best);
                else if (slice == 0)
                    out[(size_t)b * (L + 1) + (s_last + 1)] = (float)(int)(~(u32)best);
            }
        }
    }

    // --- Completion: last-arriving block finishes + resets scratch ---
    if (split_ok && tid == 0) {
        __threadfence();
        const u32 old = atomicAdd(&g_cnt[b], 1u);
        if (old == SPLIT - 1) {
            if (s_rej) {
                const u64 key = atomicMax(&g_key[b], 0ull);   // read combined max
                out[(size_t)b * (L + 1) + (s_last + 1)] = (float)(int)(~(u32)key);
            }
            g_key[b] = 0ull;     // restore for next run (graph replay safe)
            g_cnt[b] = 0u;
        }
    }
}

extern "C" void kernel_launch(void* const* d_in, const int* in_sizes, int n_in,
                              void* d_out, int out_size)
{
    // ---- order-agnostic slot resolution from sizes ----
    long long sz[6];
    for (int i = 0; i < 6; ++i) sz[i] = (i < n_in) ? (long long)in_sizes[i] : 0;

    long long mx = 0;
    for (int i = 0; i < 6; ++i) mx = (sz[i] > mx) ? sz[i] : mx;
    int ip[2], npb = 0;
    for (int i = 0; i < 6 && npb < 2; ++i) if (sz[i] == mx) ip[npb++] = i;
    if (npb < 2) ip[1] = ip[0];

    int rest[4], nr = 0;
    for (int i = 0; i < 6; ++i) if (i != ip[0] && i != ip[1] && nr < 4) rest[nr++] = i;

    long long vA = sz[rest[0]], vB = -1;
    for (int j = 1; j < 4; ++j) if (sz[rest[j]] != vA) { vB = sz[rest[j]]; break; }
    long long Bv, NTv;
    if (vB < 0) { Bv = vA; NTv = vA; }
    else {
        const bool aOK = (vA > 0) && (out_size % vA == 0) && (out_size / vA >= 2);
        const bool bOK = (vB > 0) && (out_size % vB == 0) && (out_size / vB >= 2);
        if (aOK && !bOK)      Bv = vA;
        else if (bOK && !aOK) Bv = vB;
        else                  Bv = (vA < vB) ? vA : vB;   // B <= NT
        NTv = (Bv == vA) ? vB : vA;
    }

    int iNT[2], iB[2]; int nnt = 0, nb = 0;
    for (int j = 0; j < 4; ++j) {
        if (sz[rest[j]] == NTv && nnt < 2)      iNT[nnt++] = rest[j];
        else if (nb < 2)                        iB[nb++]  = rest[j];
    }
    if (nnt < 2) iNT[1] = iNT[0];
    if (nb  < 1) { iB[0] = iNT[0]; iB[1] = iNT[1]; }
    else if (nb < 2) iB[1] = iB[0];

    const int NT = (int)NTv;
    const int B  = (int)Bv;
    const int V  = (int)(mx / (NTv > 0 ? NTv : 1));
    int L = (B > 0) ? (out_size / B - 1) : 4;
    if (L < 1) L = 1;

    dim3 grid(SPLIT, (B > 0 ? B : 1), 1);
    rejection_sample_kernel<<<grid, THREADS>>>(
        (const float*)d_in[ip[0]], (const float*)d_in[ip[1]],
        d_in[iNT[0]], d_in[iNT[1]],
        (const int*)d_in[iB[0]], (const int*)d_in[iB[1]],
        (float*)d_out, NT, V, L, B);
}